// round 8
// baseline (speedup 1.0000x reference)
#include <cuda_runtime.h>

#define NT     256
#define NBINS  10

__device__ float    g_sum[NBINS];
__device__ float    g_cnt[NBINS];
__device__ unsigned g_done;

// Per-sample: d = x_other - x_target
//   v = 1 + e^d ; l = log2(v) ; r = 1/v = p_target
//   bin = floor(20 - 20r); valid <=> bin < 10
// One predicated smem f32x2 accumulate: hist[bin][tid] += (l, 1)
__device__ __forceinline__ void process(float dd, unsigned t, unsigned hbase) {
    float d = __int_as_float(__float_as_int(dd) ^ (int)(t << 31));
    float u; asm("ex2.approx.f32 %0, %1;" : "=f"(u) : "f"(d * 1.4426950408889634f));
    float v = 1.0f + u;
    float l; asm("lg2.approx.f32 %0, %1;" : "=f"(l) : "f"(v));
    float r; asm("rcp.approx.f32 %0, %1;" : "=f"(r) : "f"(v));
    float s = fmaf(-20.0f, r, 20.0f);
    int b = (int)s;                       // trunc; in [0,20]
    unsigned long long lv;
    asm("mov.b64 %0, {%1, %2};" : "=l"(lv) : "f"(l), "f"(1.0f));
    unsigned addr = hbase + ((unsigned)b << 11);   // [bin][tid], 2048B bin stride
    asm volatile("{\n\t.reg .pred p;\n\t.reg .b64 hv;\n\t"
                 "setp.lt.s32 p, %0, 10;\n\t"
                 "@p ld.shared.b64 hv, [%1];\n\t"
                 "@p add.rn.f32x2 hv, hv, %2;\n\t"
                 "@p st.shared.b64 [%1], hv;\n\t}"
                 :: "r"(b), "r"(addr), "l"(lv) : "memory");
}

// One "pair" = 2 samples: one float4 of outputs + one uint2 of int32 targets.
// Both loads are perfectly coalesced (16B / 8B stride across lanes).
__global__ void __launch_bounds__(NT)
ghm_main(const float4* __restrict__ o4, const uint2* __restrict__ t2,
         int npairs, int n, const float* __restrict__ acc_sum,
         float* __restrict__ out, int ncta) {
    __shared__ float2 hist[NBINS][NT];    // [bin][tid] -> conflict-free LDS.64
    __shared__ float s_red[2 * NBINS];
    __shared__ unsigned s_last;

    const int tid = threadIdx.x;
    if (tid < 2 * NBINS) s_red[tid] = 0.0f;
#pragma unroll
    for (int k = 0; k < NBINS; k++) hist[k][tid] = make_float2(0.0f, 0.0f);
    __syncthreads();

    unsigned hbase;
    asm("{ .reg .u64 a; cvta.to.shared.u64 a, %1; cvt.u32.u64 %0, a; }"
        : "=r"(hbase) : "l"((void*)&hist[0][tid]));

    const int stride = gridDim.x * blockDim.x;
    int i = blockIdx.x * blockDim.x + tid;

    // 8x unroll: 16 independent coalesced loads batched up front (MLP=16)
    for (; i + 7 * stride < npairs; i += 8 * stride) {
        float4 p0 = __ldcs(o4 + i);
        float4 p1 = __ldcs(o4 + i + stride);
        float4 p2 = __ldcs(o4 + i + 2 * stride);
        float4 p3 = __ldcs(o4 + i + 3 * stride);
        float4 p4 = __ldcs(o4 + i + 4 * stride);
        float4 p5 = __ldcs(o4 + i + 5 * stride);
        float4 p6 = __ldcs(o4 + i + 6 * stride);
        float4 p7 = __ldcs(o4 + i + 7 * stride);
        uint2  t0 = __ldcs(t2 + i);
        uint2  t1 = __ldcs(t2 + i + stride);
        uint2  u2 = __ldcs(t2 + i + 2 * stride);
        uint2  u3 = __ldcs(t2 + i + 3 * stride);
        uint2  u4 = __ldcs(t2 + i + 4 * stride);
        uint2  u5 = __ldcs(t2 + i + 5 * stride);
        uint2  u6 = __ldcs(t2 + i + 6 * stride);
        uint2  u7 = __ldcs(t2 + i + 7 * stride);

        process(p0.y - p0.x, t0.x, hbase); process(p0.w - p0.z, t0.y, hbase);
        process(p1.y - p1.x, t1.x, hbase); process(p1.w - p1.z, t1.y, hbase);
        process(p2.y - p2.x, u2.x, hbase); process(p2.w - p2.z, u2.y, hbase);
        process(p3.y - p3.x, u3.x, hbase); process(p3.w - p3.z, u3.y, hbase);
        process(p4.y - p4.x, u4.x, hbase); process(p4.w - p4.z, u4.y, hbase);
        process(p5.y - p5.x, u5.x, hbase); process(p5.w - p5.z, u5.y, hbase);
        process(p6.y - p6.x, u6.x, hbase); process(p6.w - p6.z, u6.y, hbase);
        process(p7.y - p7.x, u7.x, hbase); process(p7.w - p7.z, u7.y, hbase);
    }
    for (; i < npairs; i += stride) {
        float4 p = __ldcs(o4 + i);
        uint2  t = __ldcs(t2 + i);
        process(p.y - p.x, t.x, hbase); process(p.w - p.z, t.y, hbase);
    }
    // scalar tail (n % 2 != 0) — empty for N = 2^24
    for (int s = npairs * 2 + blockIdx.x * blockDim.x + tid; s < n; s += stride) {
        const float* o = (const float*)o4;
        const unsigned* tg = (const unsigned*)t2;
        process(o[2 * s + 1] - o[2 * s], tg[s], hbase);
    }
    __syncthreads();

    // hist -> warp reduce -> block partials
#pragma unroll
    for (int k = 0; k < NBINS; k++) {
        float2 hv = hist[k][tid];
        float s = hv.x, c = hv.y;
#pragma unroll
        for (int off = 16; off > 0; off >>= 1) {
            s += __shfl_xor_sync(0xffffffffu, s, off);
            c += __shfl_xor_sync(0xffffffffu, c, off);
        }
        if ((tid & 31) == 0) {
            atomicAdd(&s_red[k],         s);
            atomicAdd(&s_red[NBINS + k], c);
        }
    }
    __syncthreads();

    // CTA partials -> global atomics (20 addresses)
    if (tid < NBINS)           atomicAdd(&g_sum[tid],         s_red[tid]);
    else if (tid < 2 * NBINS)  atomicAdd(&g_cnt[tid - NBINS], s_red[tid]);
    __threadfence();
    if (tid == 0) s_last = (atomicAdd(&g_done, 1u) == (unsigned)(ncta - 1));
    __syncthreads();

    // Last CTA: finalize, write output, reset state for next graph replay
    if (s_last && tid == 0) {
        float res = 0.0f;
#pragma unroll
        for (int b = 0; b < NBINS; b++) {
            float sb = atomicAdd(&g_sum[b], 0.0f);
            float cb = atomicAdd(&g_cnt[b], 0.0f);
            if (cb > 0.0f) {
                float na = 0.75f * acc_sum[b] + 0.25f * cb;
                res += sb * 0.6931471805599453f / na;  // ln2: sums in log2 units
            }
        }
        out[0] = res;
#pragma unroll
        for (int b = 0; b < NBINS; b++) { g_sum[b] = 0.0f; g_cnt[b] = 0.0f; }
        g_done = 0u;
    }
}

extern "C" void kernel_launch(void* const* d_in, const int* in_sizes, int n_in,
                              void* d_out, int out_size) {
    // Identify inputs BY SIZE: outputs = largest (2N f32); acc_sum = 10 f32; targets = rest (N i32)
    int i_out = 0;
    for (int i = 1; i < n_in; i++) if (in_sizes[i] > in_sizes[i_out]) i_out = i;
    int i_acc = -1;
    for (int i = 0; i < n_in; i++) if (i != i_out && in_sizes[i] == NBINS) { i_acc = i; break; }
    if (i_acc < 0) {
        for (int i = 0; i < n_in; i++)
            if (i != i_out && (i_acc < 0 || in_sizes[i] < in_sizes[i_acc])) i_acc = i;
    }
    int i_tgt = 0;
    for (int i = 0; i < n_in; i++) if (i != i_out && i != i_acc) { i_tgt = i; break; }

    const float4* o4  = (const float4*)d_in[i_out];
    const uint2*  t2  = (const uint2*)d_in[i_tgt];
    const float*  acc = (const float*)d_in[i_acc];
    const int n = in_sizes[i_tgt];
    const int npairs = n / 2;

    int sms = 148;
    cudaDeviceGetAttribute(&sms, cudaDevAttrMultiProcessorCount, 0);
    const int ncta = sms * 8;

    ghm_main<<<ncta, NT>>>(o4, t2, npairs, n, acc, (float*)d_out, ncta);
}

// round 9
// speedup vs baseline: 1.2790x; 1.2790x over previous
#include <cuda_runtime.h>

#define NT      256
#define NBINS   10
#define STAGES  4

__device__ float    g_sum[NBINS];
__device__ float    g_cnt[NBINS];
__device__ unsigned g_done;

// Dynamic smem layout (bytes):
//   [0, 16384)        outputs stages: STAGES * NT * 16
//   [16384, 24576)    targets stages: STAGES * NT * 8
//   [24576, 45056)    hist[NBINS][NT] float2  (bin stride 2048B -> conflict-free)
//   [45056, 45136)    s_red[20]
//   [45136, 45140)    s_last
#define OUTS_OFF 0
#define TGTS_OFF (STAGES * NT * 16)
#define HIST_OFF (TGTS_OFF + STAGES * NT * 8)
#define RED_OFF  (HIST_OFF + NBINS * NT * 8)
#define SMEM_BYTES (RED_OFF + 96)

extern __shared__ char smem[];

__device__ __forceinline__ unsigned smem_addr(unsigned off) {
    unsigned base;
    asm("{ .reg .u64 a; cvta.to.shared.u64 a, %1; cvt.u32.u64 %0, a; }"
        : "=r"(base) : "l"((void*)smem));
    return base + off;
}

// Per-sample: d = x_other - x_target
//   v = 1 + e^d ; l = log2(v) ; r = 1/v ; bin = floor(20 - 20r); valid <=> bin < 10
__device__ __forceinline__ void process(float dd, unsigned t, unsigned hbase) {
    float d = __int_as_float(__float_as_int(dd) ^ (int)(t << 31));
    float u; asm("ex2.approx.f32 %0, %1;" : "=f"(u) : "f"(d * 1.4426950408889634f));
    float v = 1.0f + u;
    float l; asm("lg2.approx.f32 %0, %1;" : "=f"(l) : "f"(v));
    float r; asm("rcp.approx.f32 %0, %1;" : "=f"(r) : "f"(v));
    float s = fmaf(-20.0f, r, 20.0f);
    int b = (int)s;                       // trunc; in [0,20]
    unsigned long long lv;
    asm("mov.b64 %0, {%1, %2};" : "=l"(lv) : "f"(l), "f"(1.0f));
    unsigned addr = hbase + ((unsigned)b << 11);
    asm volatile("{\n\t.reg .pred p;\n\t.reg .b64 hv;\n\t"
                 "setp.lt.s32 p, %0, 10;\n\t"
                 "@p ld.shared.b64 hv, [%1];\n\t"
                 "@p add.rn.f32x2 hv, hv, %2;\n\t"
                 "@p st.shared.b64 [%1], hv;\n\t}"
                 :: "r"(b), "r"(addr), "l"(lv) : "memory");
}

__device__ __forceinline__ void stage_in(unsigned so, unsigned st,
                                         const float4* o4, const uint2* t2, int idx) {
    asm volatile("cp.async.cg.shared.global [%0], [%1], 16;" :: "r"(so), "l"(o4 + idx));
    asm volatile("cp.async.ca.shared.global [%0], [%1], 8;"  :: "r"(st), "l"(t2 + idx));
    asm volatile("cp.async.commit_group;" ::: "memory");
}

__global__ void __launch_bounds__(NT)
ghm_main(const float4* __restrict__ o4, const uint2* __restrict__ t2,
         int npairs, int n, const float* __restrict__ acc_sum,
         float* __restrict__ out, int ncta) {
    const int tid = threadIdx.x;

    float*    s_red  = (float*)(smem + RED_OFF);
    unsigned* s_last = (unsigned*)(smem + RED_OFF + 80);
    float2*   hist   = (float2*)(smem + HIST_OFF);

    if (tid < 2 * NBINS) s_red[tid] = 0.0f;
#pragma unroll
    for (int k = 0; k < NBINS; k++) hist[k * NT + tid] = make_float2(0.0f, 0.0f);
    __syncthreads();

    const unsigned hbase = smem_addr(HIST_OFF) + tid * 8;
    const unsigned obase = smem_addr(OUTS_OFF) + tid * 16;
    const unsigned tbase = smem_addr(TGTS_OFF) + tid * 8;

    const int stride = gridDim.x * blockDim.x;
    const int gbase  = blockIdx.x * blockDim.x + tid;
    const int F = npairs / stride;        // full iterations (all threads in-range)

    // prologue: fill up to STAGES-1 stages
    const int pre = (F < STAGES - 1) ? F : (STAGES - 1);
    for (int j = 0; j < pre; j++)
        stage_in(obase + (unsigned)j * (NT * 16), tbase + (unsigned)j * (NT * 8),
                 o4, t2, gbase + j * stride);

    for (int k = 0; k < F; k++) {
        asm volatile("cp.async.wait_group 2;" ::: "memory");
        const int slot = k & (STAGES - 1);
        float4 p = *(const float4*)(smem + OUTS_OFF + ((slot * NT + tid) << 4));
        uint2  t = *(const uint2*) (smem + TGTS_OFF + ((slot * NT + tid) << 3));
        if (k + STAGES - 1 < F) {
            const int ns = (k + STAGES - 1) & (STAGES - 1);
            stage_in(obase + (unsigned)ns * (NT * 16), tbase + (unsigned)ns * (NT * 8),
                     o4, t2, gbase + (k + STAGES - 1) * stride);
        }
        process(p.y - p.x, t.x, hbase);
        process(p.w - p.z, t.y, hbase);
    }

    // tail pairs not covered by full iterations: direct loads
    for (int i = F * stride + gbase; i < npairs; i += stride) {
        float4 p = __ldcs(o4 + i);
        uint2  t = __ldcs(t2 + i);
        process(p.y - p.x, t.x, hbase);
        process(p.w - p.z, t.y, hbase);
    }
    // odd-n scalar tail — empty for N = 2^24
    for (int s = npairs * 2 + gbase; s < n; s += stride) {
        const float* o = (const float*)o4;
        const unsigned* tg = (const unsigned*)t2;
        process(o[2 * s + 1] - o[2 * s], tg[s], hbase);
    }
    __syncthreads();

    // hist -> warp reduce -> block partials
#pragma unroll
    for (int k = 0; k < NBINS; k++) {
        float2 hv = hist[k * NT + tid];
        float s = hv.x, c = hv.y;
#pragma unroll
        for (int off = 16; off > 0; off >>= 1) {
            s += __shfl_xor_sync(0xffffffffu, s, off);
            c += __shfl_xor_sync(0xffffffffu, c, off);
        }
        if ((tid & 31) == 0) {
            atomicAdd(&s_red[k],         s);
            atomicAdd(&s_red[NBINS + k], c);
        }
    }
    __syncthreads();

    if (tid < NBINS)           atomicAdd(&g_sum[tid],         s_red[tid]);
    else if (tid < 2 * NBINS)  atomicAdd(&g_cnt[tid - NBINS], s_red[tid]);
    __threadfence();
    if (tid == 0) *s_last = (atomicAdd(&g_done, 1u) == (unsigned)(ncta - 1));
    __syncthreads();

    if (*s_last && tid == 0) {
        float res = 0.0f;
#pragma unroll
        for (int b = 0; b < NBINS; b++) {
            float sb = atomicAdd(&g_sum[b], 0.0f);
            float cb = atomicAdd(&g_cnt[b], 0.0f);
            if (cb > 0.0f) {
                float na = 0.75f * acc_sum[b] + 0.25f * cb;
                res += sb * 0.6931471805599453f / na;  // ln2: sums in log2 units
            }
        }
        out[0] = res;
#pragma unroll
        for (int b = 0; b < NBINS; b++) { g_sum[b] = 0.0f; g_cnt[b] = 0.0f; }
        g_done = 0u;
    }
}

extern "C" void kernel_launch(void* const* d_in, const int* in_sizes, int n_in,
                              void* d_out, int out_size) {
    // Identify inputs BY SIZE: outputs = largest (2N f32); acc_sum = 10 f32; targets = rest (N i32)
    int i_out = 0;
    for (int i = 1; i < n_in; i++) if (in_sizes[i] > in_sizes[i_out]) i_out = i;
    int i_acc = -1;
    for (int i = 0; i < n_in; i++) if (i != i_out && in_sizes[i] == NBINS) { i_acc = i; break; }
    if (i_acc < 0) {
        for (int i = 0; i < n_in; i++)
            if (i != i_out && (i_acc < 0 || in_sizes[i] < in_sizes[i_acc])) i_acc = i;
    }
    int i_tgt = 0;
    for (int i = 0; i < n_in; i++) if (i != i_out && i != i_acc) { i_tgt = i; break; }

    const float4* o4  = (const float4*)d_in[i_out];
    const uint2*  t2  = (const uint2*)d_in[i_tgt];
    const float*  acc = (const float*)d_in[i_acc];
    const int n = in_sizes[i_tgt];
    const int npairs = n / 2;

    int sms = 148;
    cudaDeviceGetAttribute(&sms, cudaDevAttrMultiProcessorCount, 0);
    const int ncta = sms * 4;   // one resident wave at 4 CTAs/SM (smem-limited)

    cudaFuncSetAttribute(ghm_main, cudaFuncAttributeMaxDynamicSharedMemorySize, SMEM_BYTES);
    ghm_main<<<ncta, NT, SMEM_BYTES>>>(o4, t2, npairs, n, acc, (float*)d_out, ncta);
}